// round 11
// baseline (speedup 1.0000x reference)
#include <cuda_runtime.h>
#include <cuda_fp16.h>
#include <cstdint>

constexpr int Bc = 4;
constexpr int Mv = 128;
constexpr int Ev = 768;
constexpr int Rv = 768;
constexpr int Sv = Mv * (Mv + 1) / 2;   // 8256
constexpr int BSv = Bc * Sv;            // 33024

// ---------------- device scratch ----------------
__device__ float g_erow[Bc * Mv * Ev];     // [b][i][e]
__device__ float g_ecol[Bc * Ev * Mv];     // [b][e][j]
__device__ float g_rrow[Bc * Rv * Mv];
__device__ float g_rcol[Bc * Rv * Mv];
__device__ float g_mean_rel[Bc * Mv * Mv];
__device__ float g_rstd_rel[Bc * Mv * Mv];
__device__ float g_mean_ent[BSv];
__device__ float g_rstd_ent[BSv];
__device__ __half g_cDh[(size_t)BSv * Rv];             // cond fp16
__device__ __half g_A1[(size_t)Bc * Mv * Mv * Ev];     // ent_ctx fp16 [byi][j][e]
__device__ __half g_W1h[1536 * 768];                   // rows 0..767 egr_Wb, 768..1535 egr_Wg
__device__ __half g_W2h[1536 * 768];                   // rows 0..767 rge_Wb, 768..1535 rge_Wg

// ---------------- PTX helpers (baseline-target only) ----------------
__device__ __forceinline__ uint32_t s2u(const void* p) {
    uint32_t a;
    asm("{ .reg .u64 t; cvta.to.shared.u64 t, %1; cvt.u32.u64 %0, t; }" : "=r"(a) : "l"(p));
    return a;
}
__device__ __forceinline__ void ldsm_x4(uint32_t r[4], uint32_t a) {
    asm volatile("ldmatrix.sync.aligned.m8n8.x4.shared.b16 {%0,%1,%2,%3}, [%4];"
        : "=r"(r[0]), "=r"(r[1]), "=r"(r[2]), "=r"(r[3]) : "r"(a));
}
__device__ __forceinline__ void mma16816(float c[4], const uint32_t a[4], const uint32_t b[2]) {
    asm volatile("mma.sync.aligned.m16n8k16.row.col.f32.f16.f16.f32 "
        "{%0,%1,%2,%3}, {%4,%5,%6,%7}, {%8,%9}, {%0,%1,%2,%3};"
        : "+f"(c[0]), "+f"(c[1]), "+f"(c[2]), "+f"(c[3])
        : "r"(a[0]), "r"(a[1]), "r"(a[2]), "r"(a[3]), "r"(b[0]), "r"(b[1]));
}
__device__ __forceinline__ void cpa16(uint32_t dst, const void* src) {
    asm volatile("cp.async.cg.shared.global [%0], [%1], 16;" :: "r"(dst), "l"(src));
}
#define CP_COMMIT() asm volatile("cp.async.commit_group;" ::: "memory")
#define CP_WAIT0()  asm volatile("cp.async.wait_group 0;" ::: "memory")
#define CP_WAIT1()  asm volatile("cp.async.wait_group 1;" ::: "memory")

// smem stage layout (bytes), padded stride 72 fp16 = 144B (conflict-free ldmatrix)
constexpr int B_OFF = 18432;
constexpr int STGSZ = 36864;
constexpr int NSTG  = 3;
constexpr int DSMEM = NSTG * STGSZ;    // 110592 B -> 2 CTAs/SM

// ---------------- mean / rstd: warp per row, 8 rows per block ----------------
__global__ void k_meanvar(const float* __restrict__ x, int which, int nrows) {
    int row = blockIdx.x * 8 + (threadIdx.x >> 5);
    if (row >= nrows) return;
    int L = threadIdx.x & 31;
    const float4* p = (const float4*)(x + (size_t)row * 768);
    float s = 0.f, ss = 0.f;
    #pragma unroll
    for (int t = 0; t < 6; ++t) {
        float4 v = p[L + t * 32];
        s += v.x + v.y + v.z + v.w;
        ss = fmaf(v.x, v.x, ss); ss = fmaf(v.y, v.y, ss);
        ss = fmaf(v.z, v.z, ss); ss = fmaf(v.w, v.w, ss);
    }
    #pragma unroll
    for (int o = 16; o; o >>= 1) {
        s  += __shfl_xor_sync(0xffffffffu, s, o);
        ss += __shfl_xor_sync(0xffffffffu, ss, o);
    }
    if (L == 0) {
        float mean = s * (1.f / 768.f);
        float var  = ss * (1.f / 768.f) - mean * mean;
        float d    = var + 1e-12f;
        float r    = 1.f / (d * d);            // faithful: std = (var+eps)^2
        if (which == 0) { g_mean_rel[row] = mean; g_rstd_rel[row] = r; }
        else            { g_mean_ent[row] = mean; g_rstd_ent[row] = r; }
    }
}

// ---------------- convert weights to fp16 ----------------
__global__ void k_cvtw(const float* __restrict__ egWb, const float* __restrict__ egWg,
                       const float* __restrict__ rgWb, const float* __restrict__ rgWg) {
    int idx = blockIdx.x * 256 + threadIdx.x;
    if (idx >= 1536 * 768) return;
    int which = blockIdx.y;
    int row = idx / 768, col = idx - row * 768;
    const float* Wb = which ? rgWb : egWb;
    const float* Wg = which ? rgWg : egWg;
    float x = (row < 768) ? Wb[row * 768 + col] : Wg[(row - 768) * 768 + col];
    __half h = __float2half_rn(x);
    if (which) g_W2h[idx] = h;
    else       g_W1h[idx] = h;
}

// ---------------- erow / ecol (native-layout alpha/beta reads) ----------------
__global__ void k_rowcol_ent(const float* __restrict__ eh, const int* __restrict__ mir,
                             const float* __restrict__ ealpha, const float* __restrict__ ebeta) {
    int b = blockIdx.x >> 7, i = blockIdx.x & 127;
    __shared__ int mids[Mv];
    if (threadIdx.x < Mv) mids[threadIdx.x] = mir[i * Mv + threadIdx.x];
    __syncthreads();
    for (int e = threadIdx.x; e < Ev; e += 256) {
        float aR = 0.f, aC = 0.f;
        const float* arow = ealpha + e * Mv;   // ent_alpha[e][j]
        const float* brow = ebeta + e * Mv;
        #pragma unroll 4
        for (int j = 0; j < Mv; ++j) {
            float v = eh[((size_t)b * Sv + mids[j]) * Ev + e];
            aR = fmaf(v, arow[j], aR);
            aC = fmaf(v, brow[j], aC);
        }
        g_erow[((size_t)b * Mv + i) * Ev + e] = aR;     // [b][i][e]
        g_ecol[((size_t)b * Ev + e) * Mv + i] = aC;     // [b][e][j]
    }
}

// ---------------- materialize ent_ctx fp16: g_A1[byi][j][e] ----------------
__global__ void k_actx() {
    int byi = blockIdx.x;              // b*128 + i
    int b = byi >> 7;
    __shared__ float er[768];
    __shared__ float S[32][129];
    int tid = threadIdx.x;
    #pragma unroll
    for (int q = 0; q < 3; ++q) er[q * 256 + tid] = g_erow[(size_t)byi * Ev + q * 256 + tid];
    for (int t = 0; t < 24; ++t) {
        int e0 = t * 32;
        __syncthreads();
        #pragma unroll
        for (int q = 0; q < 16; ++q) {
            int idx = q * 256 + tid;
            int e = idx >> 7, j = idx & 127;
            S[e][j] = g_ecol[((size_t)b * Ev + e0 + e) * Mv + j];
        }
        __syncthreads();
        int j = tid >> 1, h = tid & 1;
        uint32_t hh[8];
        #pragma unroll
        for (int p = 0; p < 8; ++p) {
            int e = h * 16 + p * 2;
            float x0 = er[e0 + e]     * S[e][j];
            float x1 = er[e0 + e + 1] * S[e + 1][j];
            __half2 v = __float22half2_rn(make_float2(x0, x1));
            hh[p] = *(uint32_t*)&v;
        }
        __half* dst = g_A1 + ((size_t)byi * 128 + j) * 768 + e0 + h * 16;
        *(uint4*)(dst)     = make_uint4(hh[0], hh[1], hh[2], hh[3]);
        *(uint4*)(dst + 8) = make_uint4(hh[4], hh[5], hh[6], hh[7]);
    }
}

// ---------------- rcol only (rrow fused into gemm1 epilogue) ----------------
__global__ void k_rcol(const float* __restrict__ rg, const float* __restrict__ rbeta) {
    int b = blockIdx.x >> 7, k = blockIdx.x & 127;
    const float* rgb = rg + (size_t)b * Mv * Mv * Rv;
    for (int r = threadIdx.x; r < Rv; r += 256) {
        float aC = 0.f;
        const float* pcol = rgb + (size_t)k * Rv + r;       // rg[b,i,k,r], step i*Mv*Rv
        const float* brow = rbeta + r * Mv;                 // rel_beta[r][i]
        #pragma unroll 4
        for (int j = 0; j < Mv; ++j)
            aC = fmaf(pcol[(size_t)j * Mv * Rv], brow[j], aC);
        g_rcol[(b * Rv + r) * Mv + k] = aC;
    }
}

// ---------------- cond[(b,s)][r] -> fp16 ----------------
__global__ void k_cond2(const float* __restrict__ lam, const int* __restrict__ upper) {
    int b = blockIdx.y;
    int s0 = blockIdx.x * 128;
    __shared__ float rrS[32][128], rcS[32][128], lamS[32];
    __shared__ int iS[128], jS[128];
    int tid = threadIdx.x;
    if (tid < 128) {
        int s = s0 + tid;
        if (s < Sv) { int u = upper[s]; iS[tid] = u >> 7; jS[tid] = u & 127; }
        else        { iS[tid] = 0; jS[tid] = 0; }
    }
    int s_loc = tid >> 1, rh = (tid & 1) * 16;
    int s = s0 + s_loc;
    for (int rch = 0; rch < 24; ++rch) {
        int r0 = rch * 32;
        __syncthreads();
        #pragma unroll
        for (int q = 0; q < 16; ++q) {
            int idx = q * 256 + tid;
            int rk = idx >> 7, mm = idx & 127;
            rrS[rk][mm] = g_rrow[((size_t)b * Rv + r0 + rk) * Mv + mm];
            rcS[rk][mm] = g_rcol[((size_t)b * Rv + r0 + rk) * Mv + mm];
        }
        if (tid < 32) lamS[tid] = lam[r0 + tid];
        __syncthreads();
        if (s < Sv) {
            int ii = iS[s_loc], jj = jS[s_loc];
            uint32_t h8[8];
            #pragma unroll
            for (int p = 0; p < 8; ++p) {
                int r = rh + p * 2;
                float l0 = lamS[r], l1 = lamS[r + 1];
                float x0 = l0 * rrS[r][ii] * rcS[r][jj] + (1.f - l0) * rrS[r][jj] * rcS[r][ii];
                float x1 = l1 * rrS[r + 1][ii] * rcS[r + 1][jj] + (1.f - l1) * rrS[r + 1][jj] * rcS[r + 1][ii];
                __half2 h = __float22half2_rn(make_float2(x0, x1));
                h8[p] = *(uint32_t*)&h;
            }
            size_t off = ((size_t)b * Sv + s) * Rv + r0 + rh;
            *(uint4*)(g_cDh + off)     = make_uint4(h8[0], h8[1], h8[2], h8[3]);
            *(uint4*)(g_cDh + off + 8) = make_uint4(h8[4], h8[5], h8[6], h8[7]);
        }
    }
}

// ================= generic fp16 GEMM + CLN body (256 thr, 2 CTA/SM, 3-stage) =================
template <bool FUSE_RROW, typename StageF>
__device__ __forceinline__ void gemm_body(
    char* base, uint32_t sm0, int tid, int w, int L,
    StageF stage,
    const float* x_src, float* x_dst, size_t row_base, int col0,
    const float* mS, const float* sS, const float* betS, const float* gamS,
    const float* ralpha, int byi) {
    const int m0w = (w >> 1) * 32, n0w = (w & 1) * 64;

    float acc[2][8][4];
    #pragma unroll
    for (int mt = 0; mt < 2; ++mt)
        #pragma unroll
        for (int nt = 0; nt < 8; ++nt)
            #pragma unroll
            for (int q = 0; q < 4; ++q) acc[mt][nt][q] = 0.f;

    const uint32_t aBase = sm0 + (uint32_t)(m0w + (L & 15)) * 144 + (uint32_t)(L >> 4) * 16;
    const uint32_t bBase = sm0 + B_OFF
        + (uint32_t)(n0w + (L & 7) + ((L >> 4) << 3)) * 144 + (uint32_t)((L >> 3) & 1) * 16;

    stage(0, 0); CP_COMMIT();
    stage(1, 1); CP_COMMIT();

    int st_nxt = 2;
    for (int ch = 0; ch < 12; ++ch) {
        if (ch >= 10) { CP_WAIT0(); } else { CP_WAIT1(); }
        __syncthreads();
        if (ch < 10) {
            stage(ch + 2, st_nxt);
            CP_COMMIT();
            if (++st_nxt == NSTG) st_nxt = 0;
        } else if (ch == 11) {
            // prefetch epilogue x tile [128 rows x 64 cols] into stage0 (free now), stride 272B
            const float* src = x_src + row_base * 768 + col0;
            #pragma unroll
            for (int q = 0; q < 8; ++q) {
                int u = q * 256 + tid;
                int j = u >> 4, sg = u & 15;
                cpa16(sm0 + (uint32_t)j * 272 + sg * 16, src + (size_t)j * 768 + sg * 4);
            }
            CP_COMMIT();
        }
        const uint32_t off = (uint32_t)((ch % NSTG) * STGSZ);
        const uint32_t aA = aBase + off, bA = bBase + off;
        #pragma unroll
        for (int ks = 0; ks < 64; ks += 16) {
            uint32_t ah[2][4];
            #pragma unroll
            for (int mt = 0; mt < 2; ++mt)
                ldsm_x4(ah[mt], aA + mt * 2304 + ks * 2);
            #pragma unroll
            for (int np = 0; np < 4; ++np) {
                uint32_t bh[4];
                ldsm_x4(bh, bA + np * 2304 + ks * 2);
                #pragma unroll
                for (int mt = 0; mt < 2; ++mt) {
                    mma16816(acc[mt][2 * np],     ah[mt], bh);
                    mma16816(acc[mt][2 * np + 1], ah[mt], bh + 2);
                }
            }
        }
    }

    // ---- epilogue: x tile in smem (stage0), transform in place, store coalesced ----
    CP_WAIT0();
    __syncthreads();
    float* XS = (float*)base;                       // [128][68]
    const int gid = L >> 2, tig = L & 3;
    #pragma unroll
    for (int mt = 0; mt < 2; ++mt) {
        int j1 = m0w + mt * 16 + gid, j2 = j1 + 8;
        float mn1 = mS[j1], rs1 = sS[j1], mn2 = mS[j2], rs2 = sS[j2];
        #pragma unroll
        for (int nt = 0; nt < 8; ++nt) {
            int rl = (n0w >> 1) + nt * 4 + tig;
            const float* c = acc[mt][nt];
            float x1 = XS[j1 * 68 + rl], x2 = XS[j2 * 68 + rl];
            XS[j1 * 68 + rl] = (x1 - mn1) * rs1 * (c[1] + gamS[rl]) + c[0] + betS[rl];
            XS[j2 * 68 + rl] = (x2 - mn2) * rs2 * (c[3] + gamS[rl]) + c[2] + betS[rl];
        }
    }
    __syncthreads();
    {
        float* dst = x_dst + row_base * 768 + col0;
        int j = tid >> 1, c0 = (tid & 1) * 32;
        #pragma unroll
        for (int q = 0; q < 8; ++q)
            *(float4*)(dst + (size_t)j * 768 + c0 + q * 4) = *(const float4*)(XS + j * 68 + c0 + q * 4);
    }
    if (FUSE_RROW) {
        // rrow[b, col0+rl, i] = sum_j XS[j][rl] * rel_alpha[col0+rl][j]
        int rl = tid >> 2, p = tid & 3;
        const float* wA = ralpha + (size_t)(col0 + rl) * Mv;
        float s = 0.f;
        #pragma unroll 8
        for (int j = p * 32; j < p * 32 + 32; ++j)
            s = fmaf(XS[j * 68 + rl], wA[j], s);
        s += __shfl_xor_sync(0xffffffffu, s, 1);
        s += __shfl_xor_sync(0xffffffffu, s, 2);
        if (p == 0) {
            int b = byi >> 7, i = byi & 127;
            g_rrow[((size_t)b * Rv + col0 + rl) * Mv + i] = s;
        }
    }
}

// ================= GEMM1 -> rel_guided (+fused rrow) =================
__global__ __launch_bounds__(256, 2) void k_gemm1(
    const float* __restrict__ rel_hs, float* __restrict__ rel_out,
    const float* __restrict__ ebeta, const float* __restrict__ egam,
    const float* __restrict__ ralpha) {
    extern __shared__ char base[];
    const uint32_t sm0 = s2u(base);
    const int tid = threadIdx.x, w = tid >> 5, L = tid & 31;
    const int r0 = blockIdx.x * 64;
    const int byi = blockIdx.y;

    __shared__ float betS[64], gamS[64], mS[128], sS[128];
    if (tid < 64) { betS[tid] = ebeta[r0 + tid]; gamS[tid] = egam[r0 + tid]; }
    if (tid < 128) {
        mS[tid] = g_mean_rel[byi * 128 + tid];
        sS[tid] = g_rstd_rel[byi * 128 + tid];
    }

    const int cRow = tid >> 3, cSeg = tid & 7;
    auto stage = [&](int ch, int st) {
        const int k0 = ch * 64;
        uint32_t s = sm0 + (uint32_t)(st * STGSZ);
        #pragma unroll
        for (int q = 0; q < 4; ++q) {
            int row = cRow + q * 32;
            cpa16(s + (uint32_t)row * 144 + cSeg * 16,
                  g_A1 + ((size_t)byi * 128 + row) * 768 + k0 + cSeg * 8);
            int src = r0 + (row >> 1) + (row & 1) * 768;
            cpa16(s + B_OFF + (uint32_t)row * 144 + cSeg * 16,
                  g_W1h + (size_t)src * 768 + k0 + cSeg * 8);
        }
    };

    gemm_body<true>(base, sm0, tid, w, L, stage,
                    rel_hs, rel_out, (size_t)byi * 128, r0, mS, sS, betS, gamS,
                    ralpha, byi);
}

// ================= GEMM2 -> ent_guided =================
__global__ __launch_bounds__(256, 2) void k_gemm2(
    const float* __restrict__ ent_hs, float* __restrict__ ent_out,
    const float* __restrict__ rbeta, const float* __restrict__ rgam) {
    extern __shared__ char base[];
    const uint32_t sm0 = s2u(base);
    const int tid = threadIdx.x, w = tid >> 5, L = tid & 31;
    const int e0 = blockIdx.x * 64;
    const int m0 = blockIdx.y * 128;

    __shared__ float betS[64], gamS[64], mS[128], sS[128];
    if (tid < 64) { betS[tid] = rbeta[e0 + tid]; gamS[tid] = rgam[e0 + tid]; }
    if (tid < 128) {
        mS[tid] = g_mean_ent[m0 + tid];
        sS[tid] = g_rstd_ent[m0 + tid];
    }

    const int cRow = tid >> 3, cSeg = tid & 7;
    auto stage = [&](int ch, int st) {
        const int k0 = ch * 64;
        uint32_t s = sm0 + (uint32_t)(st * STGSZ);
        #pragma unroll
        for (int q = 0; q < 4; ++q) {
            int row = cRow + q * 32;
            cpa16(s + (uint32_t)row * 144 + cSeg * 16,
                  g_cDh + (size_t)(m0 + row) * Rv + k0 + cSeg * 8);
            int src = e0 + (row >> 1) + (row & 1) * 768;
            cpa16(s + B_OFF + (uint32_t)row * 144 + cSeg * 16,
                  g_W2h + (size_t)src * 768 + k0 + cSeg * 8);
        }
    };

    gemm_body<false>(base, sm0, tid, w, L, stage,
                     ent_hs, ent_out, (size_t)m0, e0, mS, sS, betS, gamS,
                     nullptr, 0);
}

// ---------------- launch ----------------
extern "C" void kernel_launch(void* const* d_in, const int* in_sizes, int n_in,
                              void* d_out, int out_size) {
    const float* ent_hs    = (const float*)d_in[0];
    const float* rel_hs    = (const float*)d_in[1];
    const float* ent_alpha = (const float*)d_in[2];
    const float* ent_beta  = (const float*)d_in[3];
    const float* rel_alpha = (const float*)d_in[4];
    const float* rel_beta  = (const float*)d_in[5];
    const float* lam       = (const float*)d_in[6];
    const float* egr_Wb    = (const float*)d_in[7];
    const float* egr_Wg    = (const float*)d_in[8];
    const float* egr_beta  = (const float*)d_in[9];
    const float* egr_gamma = (const float*)d_in[10];
    const float* rge_Wb    = (const float*)d_in[11];
    const float* rge_Wg    = (const float*)d_in[12];
    const float* rge_beta  = (const float*)d_in[13];
    const float* rge_gamma = (const float*)d_in[14];
    const int*   mirror    = (const int*)d_in[15];
    const int*   upper     = (const int*)d_in[16];

    float* ent_out = (float*)d_out;                              // [B,S,E]
    float* rel_out = (float*)d_out + (size_t)Bc * Sv * Ev;       // [B,M,M,R]

    cudaFuncSetAttribute(k_gemm1, cudaFuncAttributeMaxDynamicSharedMemorySize, DSMEM);
    cudaFuncSetAttribute(k_gemm2, cudaFuncAttributeMaxDynamicSharedMemorySize, DSMEM);

    k_meanvar<<<(Bc * Mv * Mv + 7) / 8, 256>>>(rel_hs, 0, Bc * Mv * Mv);
    k_meanvar<<<(BSv + 7) / 8, 256>>>(ent_hs, 1, BSv);
    k_cvtw<<<dim3((1536 * 768 + 255) / 256, 2), 256>>>(egr_Wb, egr_Wg, rge_Wb, rge_Wg);
    k_rowcol_ent<<<Bc * Mv, 256>>>(ent_hs, mirror, ent_alpha, ent_beta);
    k_actx<<<Bc * Mv, 256>>>();
    k_gemm1<<<dim3(12, Bc * Mv), 256, DSMEM>>>(rel_hs, rel_out, egr_beta, egr_gamma, rel_alpha);
    k_rcol<<<Bc * Mv, 256>>>(rel_out, rel_beta);
    k_cond2<<<dim3((Sv + 127) / 128, Bc), 256>>>(lam, upper);
    k_gemm2<<<dim3(12, (BSv + 127) / 128), 256, DSMEM>>>(ent_hs, ent_out, rge_beta, rge_gamma);
}

// round 12
// speedup vs baseline: 1.3623x; 1.3623x over previous
#include <cuda_runtime.h>
#include <cuda_fp16.h>
#include <cstdint>

constexpr int Bc = 4;
constexpr int Mv = 128;
constexpr int Ev = 768;
constexpr int Rv = 768;
constexpr int Sv = Mv * (Mv + 1) / 2;   // 8256
constexpr int BSv = Bc * Sv;            // 33024

// ---------------- device scratch ----------------
__device__ float g_erow[Bc * Mv * Ev];     // [b][i][e]
__device__ float g_ecol[Bc * Ev * Mv];     // [b][e][j]
__device__ float g_rrow[Bc * Rv * Mv];
__device__ float g_rcol[Bc * Rv * Mv];
__device__ float g_mean_rel[Bc * Mv * Mv];
__device__ float g_rstd_rel[Bc * Mv * Mv];
__device__ float g_mean_ent[BSv];
__device__ float g_rstd_ent[BSv];
__device__ float g_alT[Mv * Ev];           // ent_alpha^T [j][e]
__device__ float g_beT[Mv * Ev];           // ent_beta^T  [j][e]
__device__ float g_rbeT[Mv * Rv];          // rel_beta^T  [j][r]
__device__ __half g_cDh[(size_t)BSv * Rv];             // cond fp16
__device__ __half g_A1[(size_t)Bc * Mv * Mv * Ev];     // ent_ctx fp16 [byi][j][e]
__device__ __half g_W1h[1536 * 768];                   // rows 0..767 egr_Wb, 768..1535 egr_Wg
__device__ __half g_W2h[1536 * 768];                   // rows 0..767 rge_Wb, 768..1535 rge_Wg

// ---------------- PTX helpers (baseline-target only) ----------------
__device__ __forceinline__ uint32_t s2u(const void* p) {
    uint32_t a;
    asm("{ .reg .u64 t; cvta.to.shared.u64 t, %1; cvt.u32.u64 %0, t; }" : "=r"(a) : "l"(p));
    return a;
}
__device__ __forceinline__ void ldsm_x4(uint32_t r[4], uint32_t a) {
    asm volatile("ldmatrix.sync.aligned.m8n8.x4.shared.b16 {%0,%1,%2,%3}, [%4];"
        : "=r"(r[0]), "=r"(r[1]), "=r"(r[2]), "=r"(r[3]) : "r"(a));
}
__device__ __forceinline__ void mma16816(float c[4], const uint32_t a[4], const uint32_t b[2]) {
    asm volatile("mma.sync.aligned.m16n8k16.row.col.f32.f16.f16.f32 "
        "{%0,%1,%2,%3}, {%4,%5,%6,%7}, {%8,%9}, {%0,%1,%2,%3};"
        : "+f"(c[0]), "+f"(c[1]), "+f"(c[2]), "+f"(c[3])
        : "r"(a[0]), "r"(a[1]), "r"(a[2]), "r"(a[3]), "r"(b[0]), "r"(b[1]));
}
__device__ __forceinline__ void cpa16(uint32_t dst, const void* src) {
    asm volatile("cp.async.cg.shared.global [%0], [%1], 16;" :: "r"(dst), "l"(src));
}
#define CP_COMMIT() asm volatile("cp.async.commit_group;" ::: "memory")
#define CP_WAIT0()  asm volatile("cp.async.wait_group 0;" ::: "memory")
#define CP_WAIT1()  asm volatile("cp.async.wait_group 1;" ::: "memory")

// smem stage layout (bytes), padded stride 72 fp16 = 144B (conflict-free ldmatrix)
constexpr int B_OFF = 18432;
constexpr int STGSZ = 36864;
constexpr int NSTG  = 3;
constexpr int DSMEM = NSTG * STGSZ;    // 110592 B -> 2 CTAs/SM

// ---------------- mean / rstd: warp per row, 8 rows per block ----------------
__global__ void k_meanvar(const float* __restrict__ x, int which, int nrows) {
    int row = blockIdx.x * 8 + (threadIdx.x >> 5);
    if (row >= nrows) return;
    int L = threadIdx.x & 31;
    const float4* p = (const float4*)(x + (size_t)row * 768);
    float s = 0.f, ss = 0.f;
    #pragma unroll
    for (int t = 0; t < 6; ++t) {
        float4 v = p[L + t * 32];
        s += v.x + v.y + v.z + v.w;
        ss = fmaf(v.x, v.x, ss); ss = fmaf(v.y, v.y, ss);
        ss = fmaf(v.z, v.z, ss); ss = fmaf(v.w, v.w, ss);
    }
    #pragma unroll
    for (int o = 16; o; o >>= 1) {
        s  += __shfl_xor_sync(0xffffffffu, s, o);
        ss += __shfl_xor_sync(0xffffffffu, ss, o);
    }
    if (L == 0) {
        float mean = s * (1.f / 768.f);
        float var  = ss * (1.f / 768.f) - mean * mean;
        float d    = var + 1e-12f;
        float r    = 1.f / (d * d);            // faithful: std = (var+eps)^2
        if (which == 0) { g_mean_rel[row] = mean; g_rstd_rel[row] = r; }
        else            { g_mean_ent[row] = mean; g_rstd_ent[row] = r; }
    }
}

// ---------------- transpose the 3 [dim][M] params consumed lane-strided ----------------
__global__ void k_transpose3(const float* __restrict__ ea, const float* __restrict__ eb,
                             const float* __restrict__ rb) {
    int which = blockIdx.y;
    const float* in = (which == 0) ? ea : (which == 1) ? eb : rb;
    float* out = (which == 0) ? g_alT : (which == 1) ? g_beT : g_rbeT;
    int idx = blockIdx.x * 256 + threadIdx.x;
    if (idx < Mv * 768) {
        int j = idx / 768;
        int e = idx - j * 768;
        out[idx] = in[e * Mv + j];
    }
}

// ---------------- convert weights to fp16 ----------------
__global__ void k_cvtw(const float* __restrict__ egWb, const float* __restrict__ egWg,
                       const float* __restrict__ rgWb, const float* __restrict__ rgWg) {
    int idx = blockIdx.x * 256 + threadIdx.x;
    if (idx >= 1536 * 768) return;
    int which = blockIdx.y;
    int row = idx / 768, col = idx - row * 768;
    const float* Wb = which ? rgWb : egWb;
    const float* Wg = which ? rgWg : egWg;
    float x = (row < 768) ? Wb[row * 768 + col] : Wg[(row - 768) * 768 + col];
    __half h = __float2half_rn(x);
    if (which) g_W2h[idx] = h;
    else       g_W1h[idx] = h;
}

// ---------------- erow / ecol (transposed tables: lane-contiguous e) ----------------
__global__ void k_rowcol_ent(const float* __restrict__ eh, const int* __restrict__ mir) {
    int b = blockIdx.x >> 7, i = blockIdx.x & 127;
    __shared__ int mids[Mv];
    if (threadIdx.x < Mv) mids[threadIdx.x] = mir[i * Mv + threadIdx.x];
    __syncthreads();
    for (int e = threadIdx.x; e < Ev; e += 256) {
        float aR = 0.f, aC = 0.f;
        #pragma unroll 4
        for (int j = 0; j < Mv; ++j) {
            float v = eh[((size_t)b * Sv + mids[j]) * Ev + e];
            aR = fmaf(v, g_alT[j * Ev + e], aR);
            aC = fmaf(v, g_beT[j * Ev + e], aC);
        }
        g_erow[((size_t)b * Mv + i) * Ev + e] = aR;     // [b][i][e]
        g_ecol[((size_t)b * Ev + e) * Mv + i] = aC;     // [b][e][j]
    }
}

// ---------------- materialize ent_ctx fp16: g_A1[byi][j][e] ----------------
__global__ void k_actx() {
    int byi = blockIdx.x;              // b*128 + i
    int b = byi >> 7;
    __shared__ float er[768];
    __shared__ float S[32][129];
    int tid = threadIdx.x;
    #pragma unroll
    for (int q = 0; q < 3; ++q) er[q * 256 + tid] = g_erow[(size_t)byi * Ev + q * 256 + tid];
    for (int t = 0; t < 24; ++t) {
        int e0 = t * 32;
        __syncthreads();
        #pragma unroll
        for (int q = 0; q < 16; ++q) {
            int idx = q * 256 + tid;
            int e = idx >> 7, j = idx & 127;
            S[e][j] = g_ecol[((size_t)b * Ev + e0 + e) * Mv + j];
        }
        __syncthreads();
        int j = tid >> 1, h = tid & 1;
        uint32_t hh[8];
        #pragma unroll
        for (int p = 0; p < 8; ++p) {
            int e = h * 16 + p * 2;
            float x0 = er[e0 + e]     * S[e][j];
            float x1 = er[e0 + e + 1] * S[e + 1][j];
            __half2 v = __float22half2_rn(make_float2(x0, x1));
            hh[p] = *(uint32_t*)&v;
        }
        __half* dst = g_A1 + ((size_t)byi * 128 + j) * 768 + e0 + h * 16;
        *(uint4*)(dst)     = make_uint4(hh[0], hh[1], hh[2], hh[3]);
        *(uint4*)(dst + 8) = make_uint4(hh[4], hh[5], hh[6], hh[7]);
    }
}

// ---------------- rcol only (rrow fused into gemm1 epilogue) ----------------
__global__ void k_rcol(const float* __restrict__ rg) {
    int b = blockIdx.x >> 7, k = blockIdx.x & 127;
    const float* rgb = rg + (size_t)b * Mv * Mv * Rv;
    for (int r = threadIdx.x; r < Rv; r += 256) {
        float aC = 0.f;
        const float* pcol = rgb + (size_t)k * Rv + r;       // rg[b,i,k,r], step i*Mv*Rv
        #pragma unroll 4
        for (int j = 0; j < Mv; ++j)
            aC = fmaf(pcol[(size_t)j * Mv * Rv], g_rbeT[j * Rv + r], aC);
        g_rcol[(b * Rv + r) * Mv + k] = aC;
    }
}

// ---------------- cond[(b,s)][r] -> fp16 ----------------
__global__ void k_cond2(const float* __restrict__ lam, const int* __restrict__ upper) {
    int b = blockIdx.y;
    int s0 = blockIdx.x * 128;
    __shared__ float rrS[32][128], rcS[32][128], lamS[32];
    __shared__ int iS[128], jS[128];
    int tid = threadIdx.x;
    if (tid < 128) {
        int s = s0 + tid;
        if (s < Sv) { int u = upper[s]; iS[tid] = u >> 7; jS[tid] = u & 127; }
        else        { iS[tid] = 0; jS[tid] = 0; }
    }
    int s_loc = tid >> 1, rh = (tid & 1) * 16;
    int s = s0 + s_loc;
    for (int rch = 0; rch < 24; ++rch) {
        int r0 = rch * 32;
        __syncthreads();
        #pragma unroll
        for (int q = 0; q < 16; ++q) {
            int idx = q * 256 + tid;
            int rk = idx >> 7, mm = idx & 127;
            rrS[rk][mm] = g_rrow[((size_t)b * Rv + r0 + rk) * Mv + mm];
            rcS[rk][mm] = g_rcol[((size_t)b * Rv + r0 + rk) * Mv + mm];
        }
        if (tid < 32) lamS[tid] = lam[r0 + tid];
        __syncthreads();
        if (s < Sv) {
            int ii = iS[s_loc], jj = jS[s_loc];
            uint32_t h8[8];
            #pragma unroll
            for (int p = 0; p < 8; ++p) {
                int r = rh + p * 2;
                float l0 = lamS[r], l1 = lamS[r + 1];
                float x0 = l0 * rrS[r][ii] * rcS[r][jj] + (1.f - l0) * rrS[r][jj] * rcS[r][ii];
                float x1 = l1 * rrS[r + 1][ii] * rcS[r + 1][jj] + (1.f - l1) * rrS[r + 1][jj] * rcS[r + 1][ii];
                __half2 h = __float22half2_rn(make_float2(x0, x1));
                h8[p] = *(uint32_t*)&h;
            }
            size_t off = ((size_t)b * Sv + s) * Rv + r0 + rh;
            *(uint4*)(g_cDh + off)     = make_uint4(h8[0], h8[1], h8[2], h8[3]);
            *(uint4*)(g_cDh + off + 8) = make_uint4(h8[4], h8[5], h8[6], h8[7]);
        }
    }
}

// ================= generic fp16 GEMM + CLN body (256 thr, 2 CTA/SM, 3-stage) =================
template <bool FUSE_RROW, typename StageF>
__device__ __forceinline__ void gemm_body(
    char* base, uint32_t sm0, int tid, int w, int L,
    StageF stage,
    const float* x_src, float* x_dst, size_t row_base, int col0,
    const float* mS, const float* sS, const float* betS, const float* gamS,
    const float* ralpha, int byi) {
    const int m0w = (w >> 1) * 32, n0w = (w & 1) * 64;

    float acc[2][8][4];
    #pragma unroll
    for (int mt = 0; mt < 2; ++mt)
        #pragma unroll
        for (int nt = 0; nt < 8; ++nt)
            #pragma unroll
            for (int q = 0; q < 4; ++q) acc[mt][nt][q] = 0.f;

    const uint32_t aBase = sm0 + (uint32_t)(m0w + (L & 15)) * 144 + (uint32_t)(L >> 4) * 16;
    const uint32_t bBase = sm0 + B_OFF
        + (uint32_t)(n0w + (L & 7) + ((L >> 4) << 3)) * 144 + (uint32_t)((L >> 3) & 1) * 16;

    stage(0, 0); CP_COMMIT();
    stage(1, 1); CP_COMMIT();

    int st_nxt = 2;
    for (int ch = 0; ch < 12; ++ch) {
        if (ch >= 10) { CP_WAIT0(); } else { CP_WAIT1(); }
        __syncthreads();
        if (ch < 10) {
            stage(ch + 2, st_nxt);
            CP_COMMIT();
            if (++st_nxt == NSTG) st_nxt = 0;
        } else if (ch == 11) {
            // prefetch epilogue x tile [128 rows x 64 cols] into stage0 (free now), stride 272B
            const float* src = x_src + row_base * 768 + col0;
            #pragma unroll
            for (int q = 0; q < 8; ++q) {
                int u = q * 256 + tid;
                int j = u >> 4, sg = u & 15;
                cpa16(sm0 + (uint32_t)j * 272 + sg * 16, src + (size_t)j * 768 + sg * 4);
            }
            CP_COMMIT();
        }
        const uint32_t off = (uint32_t)((ch % NSTG) * STGSZ);
        const uint32_t aA = aBase + off, bA = bBase + off;
        #pragma unroll
        for (int ks = 0; ks < 64; ks += 16) {
            uint32_t ah[2][4];
            #pragma unroll
            for (int mt = 0; mt < 2; ++mt)
                ldsm_x4(ah[mt], aA + mt * 2304 + ks * 2);
            #pragma unroll
            for (int np = 0; np < 4; ++np) {
                uint32_t bh[4];
                ldsm_x4(bh, bA + np * 2304 + ks * 2);
                #pragma unroll
                for (int mt = 0; mt < 2; ++mt) {
                    mma16816(acc[mt][2 * np],     ah[mt], bh);
                    mma16816(acc[mt][2 * np + 1], ah[mt], bh + 2);
                }
            }
        }
    }

    // ---- epilogue: x tile in smem (stage0), transform in place, store coalesced ----
    CP_WAIT0();
    __syncthreads();
    float* XS = (float*)base;                       // [128][68]
    const int gid = L >> 2, tig = L & 3;
    #pragma unroll
    for (int mt = 0; mt < 2; ++mt) {
        int j1 = m0w + mt * 16 + gid, j2 = j1 + 8;
        float mn1 = mS[j1], rs1 = sS[j1], mn2 = mS[j2], rs2 = sS[j2];
        #pragma unroll
        for (int nt = 0; nt < 8; ++nt) {
            int rl = (n0w >> 1) + nt * 4 + tig;
            const float* c = acc[mt][nt];
            float x1 = XS[j1 * 68 + rl], x2 = XS[j2 * 68 + rl];
            XS[j1 * 68 + rl] = (x1 - mn1) * rs1 * (c[1] + gamS[rl]) + c[0] + betS[rl];
            XS[j2 * 68 + rl] = (x2 - mn2) * rs2 * (c[3] + gamS[rl]) + c[2] + betS[rl];
        }
    }
    __syncthreads();
    {
        float* dst = x_dst + row_base * 768 + col0;
        int j = tid >> 1, c0 = (tid & 1) * 32;
        #pragma unroll
        for (int q = 0; q < 8; ++q)
            *(float4*)(dst + (size_t)j * 768 + c0 + q * 4) = *(const float4*)(XS + j * 68 + c0 + q * 4);
    }
    if (FUSE_RROW) {
        // rrow[b, col0+rl, i] = sum_j XS[j][rl] * rel_alpha[col0+rl][j]  (contiguous j per thread)
        int rl = tid >> 2, p = tid & 3;
        const float* wA = ralpha + (size_t)(col0 + rl) * Mv;
        float s = 0.f;
        #pragma unroll 8
        for (int j = p * 32; j < p * 32 + 32; ++j)
            s = fmaf(XS[j * 68 + rl], wA[j], s);
        s += __shfl_xor_sync(0xffffffffu, s, 1);
        s += __shfl_xor_sync(0xffffffffu, s, 2);
        if (p == 0) {
            int b = byi >> 7, i = byi & 127;
            g_rrow[((size_t)b * Rv + col0 + rl) * Mv + i] = s;
        }
    }
}

// ================= GEMM1 -> rel_guided (+fused rrow) =================
__global__ __launch_bounds__(256, 2) void k_gemm1(
    const float* __restrict__ rel_hs, float* __restrict__ rel_out,
    const float* __restrict__ ebeta, const float* __restrict__ egam,
    const float* __restrict__ ralpha) {
    extern __shared__ char base[];
    const uint32_t sm0 = s2u(base);
    const int tid = threadIdx.x, w = tid >> 5, L = tid & 31;
    const int r0 = blockIdx.x * 64;
    const int byi = blockIdx.y;

    __shared__ float betS[64], gamS[64], mS[128], sS[128];
    if (tid < 64) { betS[tid] = ebeta[r0 + tid]; gamS[tid] = egam[r0 + tid]; }
    if (tid < 128) {
        mS[tid] = g_mean_rel[byi * 128 + tid];
        sS[tid] = g_rstd_rel[byi * 128 + tid];
    }

    const int cRow = tid >> 3, cSeg = tid & 7;
    auto stage = [&](int ch, int st) {
        const int k0 = ch * 64;
        uint32_t s = sm0 + (uint32_t)(st * STGSZ);
        #pragma unroll
        for (int q = 0; q < 4; ++q) {
            int row = cRow + q * 32;
            cpa16(s + (uint32_t)row * 144 + cSeg * 16,
                  g_A1 + ((size_t)byi * 128 + row) * 768 + k0 + cSeg * 8);
            int src = r0 + (row >> 1) + (row & 1) * 768;
            cpa16(s + B_OFF + (uint32_t)row * 144 + cSeg * 16,
                  g_W1h + (size_t)src * 768 + k0 + cSeg * 8);
        }
    };

    gemm_body<true>(base, sm0, tid, w, L, stage,
                    rel_hs, rel_out, (size_t)byi * 128, r0, mS, sS, betS, gamS,
                    ralpha, byi);
}

// ================= GEMM2 -> ent_guided =================
__global__ __launch_bounds__(256, 2) void k_gemm2(
    const float* __restrict__ ent_hs, float* __restrict__ ent_out,
    const float* __restrict__ rbeta, const float* __restrict__ rgam) {
    extern __shared__ char base[];
    const uint32_t sm0 = s2u(base);
    const int tid = threadIdx.x, w = tid >> 5, L = tid & 31;
    const int e0 = blockIdx.x * 64;
    const int m0 = blockIdx.y * 128;

    __shared__ float betS[64], gamS[64], mS[128], sS[128];
    if (tid < 64) { betS[tid] = rbeta[e0 + tid]; gamS[tid] = rgam[e0 + tid]; }
    if (tid < 128) {
        mS[tid] = g_mean_ent[m0 + tid];
        sS[tid] = g_rstd_ent[m0 + tid];
    }

    const int cRow = tid >> 3, cSeg = tid & 7;
    auto stage = [&](int ch, int st) {
        const int k0 = ch * 64;
        uint32_t s = sm0 + (uint32_t)(st * STGSZ);
        #pragma unroll
        for (int q = 0; q < 4; ++q) {
            int row = cRow + q * 32;
            cpa16(s + (uint32_t)row * 144 + cSeg * 16,
                  g_cDh + (size_t)(m0 + row) * Rv + k0 + cSeg * 8);
            int src = e0 + (row >> 1) + (row & 1) * 768;
            cpa16(s + B_OFF + (uint32_t)row * 144 + cSeg * 16,
                  g_W2h + (size_t)src * 768 + k0 + cSeg * 8);
        }
    };

    gemm_body<false>(base, sm0, tid, w, L, stage,
                     ent_hs, ent_out, (size_t)m0, e0, mS, sS, betS, gamS,
                     nullptr, 0);
}

// ---------------- launch ----------------
extern "C" void kernel_launch(void* const* d_in, const int* in_sizes, int n_in,
                              void* d_out, int out_size) {
    const float* ent_hs    = (const float*)d_in[0];
    const float* rel_hs    = (const float*)d_in[1];
    const float* ent_alpha = (const float*)d_in[2];
    const float* ent_beta  = (const float*)d_in[3];
    const float* rel_alpha = (const float*)d_in[4];
    const float* rel_beta  = (const float*)d_in[5];
    const float* lam       = (const float*)d_in[6];
    const float* egr_Wb    = (const float*)d_in[7];
    const float* egr_Wg    = (const float*)d_in[8];
    const float* egr_beta  = (const float*)d_in[9];
    const float* egr_gamma = (const float*)d_in[10];
    const float* rge_Wb    = (const float*)d_in[11];
    const float* rge_Wg    = (const float*)d_in[12];
    const float* rge_beta  = (const float*)d_in[13];
    const float* rge_gamma = (const float*)d_in[14];
    const int*   mirror    = (const int*)d_in[15];
    const int*   upper     = (const int*)d_in[16];

    float* ent_out = (float*)d_out;                              // [B,S,E]
    float* rel_out = (float*)d_out + (size_t)Bc * Sv * Ev;       // [B,M,M,R]

    cudaFuncSetAttribute(k_gemm1, cudaFuncAttributeMaxDynamicSharedMemorySize, DSMEM);
    cudaFuncSetAttribute(k_gemm2, cudaFuncAttributeMaxDynamicSharedMemorySize, DSMEM);

    k_meanvar<<<(Bc * Mv * Mv + 7) / 8, 256>>>(rel_hs, 0, Bc * Mv * Mv);
    k_meanvar<<<(BSv + 7) / 8, 256>>>(ent_hs, 1, BSv);
    k_transpose3<<<dim3((Mv * 768 + 255) / 256, 3), 256>>>(ent_alpha, ent_beta, rel_beta);
    k_cvtw<<<dim3((1536 * 768 + 255) / 256, 2), 256>>>(egr_Wb, egr_Wg, rge_Wb, rge_Wg);
    k_rowcol_ent<<<Bc * Mv, 256>>>(ent_hs, mirror);
    k_actx<<<Bc * Mv, 256>>>();
    k_gemm1<<<dim3(12, Bc * Mv), 256, DSMEM>>>(rel_hs, rel_out, egr_beta, egr_gamma, rel_alpha);
    k_rcol<<<Bc * Mv, 256>>>(rel_out);
    k_cond2<<<dim3((Sv + 127) / 128, Bc), 256>>>(lam, upper);
    k_gemm2<<<dim3(12, (BSv + 127) / 128), 256, DSMEM>>>(ent_hs, ent_out, rge_beta, rge_gamma);
}

// round 14
// speedup vs baseline: 1.3988x; 1.0267x over previous
#include <cuda_runtime.h>
#include <cuda_fp16.h>
#include <cstdint>

constexpr int Bc = 4;
constexpr int Mv = 128;
constexpr int Ev = 768;
constexpr int Rv = 768;
constexpr int Sv = Mv * (Mv + 1) / 2;   // 8256
constexpr int BSv = Bc * Sv;            // 33024

// ---------------- device scratch ----------------
__device__ float g_erow[Bc * Mv * Ev];     // [b][i][e]
__device__ float g_ecol[Bc * Ev * Mv];     // [b][e][j]
__device__ float g_rrow[Bc * Rv * Mv];
__device__ float g_rcol[Bc * Rv * Mv];
__device__ float g_mean_rel[Bc * Mv * Mv];
__device__ float g_rstd_rel[Bc * Mv * Mv];
__device__ float g_mean_ent[BSv];
__device__ float g_rstd_ent[BSv];
__device__ float g_alT[Mv * Ev];           // ent_alpha^T [j][e]
__device__ float g_beT[Mv * Ev];           // ent_beta^T  [j][e]
__device__ float g_rbeT[Mv * Rv];          // rel_beta^T  [j][r]
__device__ __half g_cDh[(size_t)BSv * Rv];             // cond fp16
__device__ __half g_A1[(size_t)Bc * Mv * Mv * Ev];     // ent_ctx fp16 [byi][j][e]
__device__ __half g_W1h[1536 * 768];                   // rows 0..767 egr_Wb, 768..1535 egr_Wg
__device__ __half g_W2h[1536 * 768];                   // rows 0..767 rge_Wb, 768..1535 rge_Wg

// ---------------- PTX helpers (baseline-target only) ----------------
__device__ __forceinline__ uint32_t s2u(const void* p) {
    uint32_t a;
    asm("{ .reg .u64 t; cvta.to.shared.u64 t, %1; cvt.u32.u64 %0, t; }" : "=r"(a) : "l"(p));
    return a;
}
__device__ __forceinline__ void ldsm_x4(uint32_t r[4], uint32_t a) {
    asm volatile("ldmatrix.sync.aligned.m8n8.x4.shared.b16 {%0,%1,%2,%3}, [%4];"
        : "=r"(r[0]), "=r"(r[1]), "=r"(r[2]), "=r"(r[3]) : "r"(a));
}
__device__ __forceinline__ void mma16816(float c[4], const uint32_t a[4], const uint32_t b[2]) {
    asm volatile("mma.sync.aligned.m16n8k16.row.col.f32.f16.f16.f32 "
        "{%0,%1,%2,%3}, {%4,%5,%6,%7}, {%8,%9}, {%0,%1,%2,%3};"
        : "+f"(c[0]), "+f"(c[1]), "+f"(c[2]), "+f"(c[3])
        : "r"(a[0]), "r"(a[1]), "r"(a[2]), "r"(a[3]), "r"(b[0]), "r"(b[1]));
}
__device__ __forceinline__ void cpa16(uint32_t dst, const void* src) {
    asm volatile("cp.async.cg.shared.global [%0], [%1], 16;" :: "r"(dst), "l"(src));
}
#define CP_COMMIT() asm volatile("cp.async.commit_group;" ::: "memory")
#define CP_WAIT0()  asm volatile("cp.async.wait_group 0;" ::: "memory")
#define CP_WAIT1()  asm volatile("cp.async.wait_group 1;" ::: "memory")

// smem stage layout (bytes), padded stride 72 fp16 = 144B (conflict-free ldmatrix)
constexpr int B_OFF = 18432;
constexpr int STGSZ = 36864;
constexpr int NSTG  = 3;
constexpr int DSMEM = NSTG * STGSZ;    // 110592 B -> 2 CTAs/SM

// block-range dispatch constants for k_pre
constexpr int NB_MVREL = (Bc * Mv * Mv + 7) / 8;   // 8192
constexpr int NB_MVENT = (BSv + 7) / 8;            // 4128
constexpr int NB_TRAN  = 3 * (Mv * 768 / 256);     // 1152
constexpr int NB_CVT   = 2 * (1536 * 768 / 256);   // 9216
constexpr int NB_PRE   = NB_MVREL + NB_MVENT + NB_TRAN + NB_CVT;

// ---------------- merged preamble: meanvar x2 + transpose3 + cvtw ----------------
__device__ __forceinline__ void mv_body(const float* __restrict__ x, int row, int nrows,
                                        float* __restrict__ mdst, float* __restrict__ rdst,
                                        int L) {
    if (row >= nrows) return;
    const float4* p = (const float4*)(x + (size_t)row * 768);
    float s = 0.f, ss = 0.f;
    #pragma unroll
    for (int t = 0; t < 6; ++t) {
        float4 v = p[L + t * 32];
        s += v.x + v.y + v.z + v.w;
        ss = fmaf(v.x, v.x, ss); ss = fmaf(v.y, v.y, ss);
        ss = fmaf(v.z, v.z, ss); ss = fmaf(v.w, v.w, ss);
    }
    #pragma unroll
    for (int o = 16; o; o >>= 1) {
        s  += __shfl_xor_sync(0xffffffffu, s, o);
        ss += __shfl_xor_sync(0xffffffffu, ss, o);
    }
    if (L == 0) {
        float mean = s * (1.f / 768.f);
        float var  = ss * (1.f / 768.f) - mean * mean;
        float d    = var + 1e-12f;
        mdst[row] = mean;
        rdst[row] = 1.f / (d * d);             // faithful: std = (var+eps)^2
    }
}

__global__ void k_pre(const float* __restrict__ rel_hs, const float* __restrict__ ent_hs,
                      const float* __restrict__ ea, const float* __restrict__ eb,
                      const float* __restrict__ rb,
                      const float* __restrict__ egWb, const float* __restrict__ egWg,
                      const float* __restrict__ rgWb, const float* __restrict__ rgWg) {
    int bx = blockIdx.x;
    int tid = threadIdx.x, L = tid & 31;
    if (bx < NB_MVREL) {
        mv_body(rel_hs, bx * 8 + (tid >> 5), Bc * Mv * Mv, g_mean_rel, g_rstd_rel, L);
    } else if (bx < NB_MVREL + NB_MVENT) {
        mv_body(ent_hs, (bx - NB_MVREL) * 8 + (tid >> 5), BSv, g_mean_ent, g_rstd_ent, L);
    } else if (bx < NB_MVREL + NB_MVENT + NB_TRAN) {
        int g = (bx - NB_MVREL - NB_MVENT) * 256 + tid;    // over 3*98304
        int which = g / (Mv * 768);
        int idx = g - which * (Mv * 768);
        const float* in = (which == 0) ? ea : (which == 1) ? eb : rb;
        float* out = (which == 0) ? g_alT : (which == 1) ? g_beT : g_rbeT;
        int j = idx / 768, e = idx - j * 768;
        out[idx] = in[e * Mv + j];
    } else {
        int g = (bx - NB_MVREL - NB_MVENT - NB_TRAN) * 256 + tid;  // over 2*1179648
        int which = g / (1536 * 768);
        int idx = g - which * (1536 * 768);
        int row = idx / 768, col = idx - row * 768;
        const float* Wb = which ? rgWb : egWb;
        const float* Wg = which ? rgWg : egWg;
        float x = (row < 768) ? Wb[row * 768 + col] : Wg[(row - 768) * 768 + col];
        __half h = __float2half_rn(x);
        if (which) g_W2h[idx] = h;
        else       g_W1h[idx] = h;
    }
}

// ---------------- erow / ecol: one e per thread, 3-way e-split ----------------
__global__ void k_rowcol_ent(const float* __restrict__ eh, const int* __restrict__ mir) {
    int b = blockIdx.x >> 7, i = blockIdx.x & 127;
    int e = blockIdx.y * 256 + threadIdx.x;
    __shared__ int mids[Mv];
    if (threadIdx.x < Mv) mids[threadIdx.x] = mir[i * Mv + threadIdx.x];
    __syncthreads();
    float aR = 0.f, aC = 0.f;
    #pragma unroll 4
    for (int j = 0; j < Mv; ++j) {
        float v = eh[((size_t)b * Sv + mids[j]) * Ev + e];
        aR = fmaf(v, g_alT[j * Ev + e], aR);
        aC = fmaf(v, g_beT[j * Ev + e], aC);
    }
    g_erow[((size_t)b * Mv + i) * Ev + e] = aR;     // [b][i][e]
    g_ecol[((size_t)b * Ev + e) * Mv + i] = aC;     // [b][e][j]
}

// ---------------- materialize ent_ctx fp16: g_A1[byi][j][e], 2-way e-split ----------------
__global__ void k_actx() {
    int byi = blockIdx.x;              // b*128 + i
    int b = byi >> 7;
    int ebase = blockIdx.y * 384;
    __shared__ float er[384];
    __shared__ float S[32][129];
    int tid = threadIdx.x;
    er[tid < 256 ? tid : 0] = g_erow[(size_t)byi * Ev + ebase + (tid < 256 ? tid : 0)];
    if (tid < 128) er[256 + tid] = g_erow[(size_t)byi * Ev + ebase + 256 + tid];
    for (int t = 0; t < 12; ++t) {
        int e0 = ebase + t * 32;
        __syncthreads();
        #pragma unroll
        for (int q = 0; q < 16; ++q) {
            int idx = q * 256 + tid;
            int e = idx >> 7, j = idx & 127;
            S[e][j] = g_ecol[((size_t)b * Ev + e0 + e) * Mv + j];
        }
        __syncthreads();
        int j = tid >> 1, h = tid & 1;
        uint32_t hh[8];
        #pragma unroll
        for (int p = 0; p < 8; ++p) {
            int e = h * 16 + p * 2;
            float x0 = er[t * 32 + e]     * S[e][j];
            float x1 = er[t * 32 + e + 1] * S[e + 1][j];
            __half2 v = __float22half2_rn(make_float2(x0, x1));
            hh[p] = *(uint32_t*)&v;
        }
        __half* dst = g_A1 + ((size_t)byi * 128 + j) * 768 + e0 + h * 16;
        *(uint4*)(dst)     = make_uint4(hh[0], hh[1], hh[2], hh[3]);
        *(uint4*)(dst + 8) = make_uint4(hh[4], hh[5], hh[6], hh[7]);
    }
}

// ---------------- rcol only (rrow fused into gemm1 epilogue) ----------------
__global__ void k_rcol(const float* __restrict__ rg) {
    int b = blockIdx.x >> 7, k = blockIdx.x & 127;
    const float* rgb = rg + (size_t)b * Mv * Mv * Rv;
    for (int r = threadIdx.x; r < Rv; r += 256) {
        float aC = 0.f;
        const float* pcol = rgb + (size_t)k * Rv + r;       // rg[b,i,k,r], step i*Mv*Rv
        #pragma unroll 4
        for (int j = 0; j < Mv; ++j)
            aC = fmaf(pcol[(size_t)j * Mv * Rv], g_rbeT[j * Rv + r], aC);
        g_rcol[(b * Rv + r) * Mv + k] = aC;
    }
}

// ---------------- cond[(b,s)][r] -> fp16, 2-way r-split ----------------
__global__ void k_cond2(const float* __restrict__ lam, const int* __restrict__ upper) {
    int b = blockIdx.y;
    int s0 = blockIdx.x * 128;
    int rchBase = blockIdx.z * 12;
    __shared__ float rrS[32][128], rcS[32][128], lamS[32];
    __shared__ int iS[128], jS[128];
    int tid = threadIdx.x;
    if (tid < 128) {
        int s = s0 + tid;
        if (s < Sv) { int u = upper[s]; iS[tid] = u >> 7; jS[tid] = u & 127; }
        else        { iS[tid] = 0; jS[tid] = 0; }
    }
    int s_loc = tid >> 1, rh = (tid & 1) * 16;
    int s = s0 + s_loc;
    for (int rch = rchBase; rch < rchBase + 12; ++rch) {
        int r0 = rch * 32;
        __syncthreads();
        #pragma unroll
        for (int q = 0; q < 16; ++q) {
            int idx = q * 256 + tid;
            int rk = idx >> 7, mm = idx & 127;
            rrS[rk][mm] = g_rrow[((size_t)b * Rv + r0 + rk) * Mv + mm];
            rcS[rk][mm] = g_rcol[((size_t)b * Rv + r0 + rk) * Mv + mm];
        }
        if (tid < 32) lamS[tid] = lam[r0 + tid];
        __syncthreads();
        if (s < Sv) {
            int ii = iS[s_loc], jj = jS[s_loc];
            uint32_t h8[8];
            #pragma unroll
            for (int p = 0; p < 8; ++p) {
                int r = rh + p * 2;
                float l0 = lamS[r], l1 = lamS[r + 1];
                float x0 = l0 * rrS[r][ii] * rcS[r][jj] + (1.f - l0) * rrS[r][jj] * rcS[r][ii];
                float x1 = l1 * rrS[r + 1][ii] * rcS[r + 1][jj] + (1.f - l1) * rrS[r + 1][jj] * rcS[r + 1][ii];
                __half2 h = __float22half2_rn(make_float2(x0, x1));
                h8[p] = *(uint32_t*)&h;
            }
            size_t off = ((size_t)b * Sv + s) * Rv + r0 + rh;
            *(uint4*)(g_cDh + off)     = make_uint4(h8[0], h8[1], h8[2], h8[3]);
            *(uint4*)(g_cDh + off + 8) = make_uint4(h8[4], h8[5], h8[6], h8[7]);
        }
    }
}

// ================= generic fp16 GEMM + CLN body (256 thr, 2 CTA/SM, 3-stage) =================
template <bool FUSE_RROW, typename StageF>
__device__ __forceinline__ void gemm_body(
    char* base, uint32_t sm0, int tid, int w, int L,
    StageF stage,
    const float* x_src, float* x_dst, size_t row_base, int col0,
    const float* mS, const float* sS, const float* betS, const float* gamS,
    const float* ralpha, int byi) {
    const int m0w = (w >> 1) * 32, n0w = (w & 1) * 64;

    float acc[2][8][4];
    #pragma unroll
    for (int mt = 0; mt < 2; ++mt)
        #pragma unroll
        for (int nt = 0; nt < 8; ++nt)
            #pragma unroll
            for (int q = 0; q < 4; ++q) acc[mt][nt][q] = 0.f;

    const uint32_t aBase = sm0 + (uint32_t)(m0w + (L & 15)) * 144 + (uint32_t)(L >> 4) * 16;
    const uint32_t bBase = sm0 + B_OFF
        + (uint32_t)(n0w + (L & 7) + ((L >> 4) << 3)) * 144 + (uint32_t)((L >> 3) & 1) * 16;

    stage(0, 0); CP_COMMIT();
    stage(1, 1); CP_COMMIT();

    int st_nxt = 2;
    for (int ch = 0; ch < 12; ++ch) {
        if (ch >= 10) { CP_WAIT0(); } else { CP_WAIT1(); }
        __syncthreads();
        if (ch < 10) {
            stage(ch + 2, st_nxt);
            CP_COMMIT();
            if (++st_nxt == NSTG) st_nxt = 0;
        } else if (ch == 11) {
            // prefetch epilogue x tile [128 rows x 64 cols] into stage0 (free now), stride 272B
            const float* src = x_src + row_base * 768 + col0;
            #pragma unroll
            for (int q = 0; q < 8; ++q) {
                int u = q * 256 + tid;
                int j = u >> 4, sg = u & 15;
                cpa16(sm0 + (uint32_t)j * 272 + sg * 16, src + (size_t)j * 768 + sg * 4);
            }
            CP_COMMIT();
        }
        const uint32_t off = (uint32_t)((ch % NSTG) * STGSZ);
        const uint32_t aA = aBase + off, bA = bBase + off;
        #pragma unroll
        for (int ks = 0; ks < 64; ks += 16) {
            uint32_t ah[2][4];
            #pragma unroll
            for (int mt = 0; mt < 2; ++mt)
                ldsm_x4(ah[mt], aA + mt * 2304 + ks * 2);
            #pragma unroll
            for (int np = 0; np < 4; ++np) {
                uint32_t bh[4];
                ldsm_x4(bh, bA + np * 2304 + ks * 2);
                #pragma unroll
                for (int mt = 0; mt < 2; ++mt) {
                    mma16816(acc[mt][2 * np],     ah[mt], bh);
                    mma16816(acc[mt][2 * np + 1], ah[mt], bh + 2);
                }
            }
        }
    }

    // ---- epilogue: x tile in smem (stage0), transform in place, store coalesced ----
    CP_WAIT0();
    __syncthreads();
    float* XS = (float*)base;                       // [128][68]
    const int gid = L >> 2, tig = L & 3;
    #pragma unroll
    for (int mt = 0; mt < 2; ++mt) {
        int j1 = m0w + mt * 16 + gid, j2 = j1 + 8;
        float mn1 = mS[j1], rs1 = sS[j1], mn2 = mS[j2], rs2 = sS[j2];
        #pragma unroll
        for (int nt = 0; nt < 8; ++nt) {
            int rl = (n0w >> 1) + nt * 4 + tig;
            const float* c = acc[mt][nt];
            float x1 = XS[j1 * 68 + rl], x2 = XS[j2 * 68 + rl];
            XS[j1 * 68 + rl] = (x1 - mn1) * rs1 * (c[1] + gamS[rl]) + c[0] + betS[rl];
            XS[j2 * 68 + rl] = (x2 - mn2) * rs2 * (c[3] + gamS[rl]) + c[2] + betS[rl];
        }
    }
    __syncthreads();
    {
        float* dst = x_dst + row_base * 768 + col0;
        int j = tid >> 1, c0 = (tid & 1) * 32;
        #pragma unroll
        for (int q = 0; q < 8; ++q)
            *(float4*)(dst + (size_t)j * 768 + c0 + q * 4) = *(const float4*)(XS + j * 68 + c0 + q * 4);
    }
    if (FUSE_RROW) {
        // rrow[b, col0+rl, i] = sum_j XS[j][rl] * rel_alpha[col0+rl][j]  (contiguous j per thread)
        int rl = tid >> 2, p = tid & 3;
        const float* wA = ralpha + (size_t)(col0 + rl) * Mv;
        float s = 0.f;
        #pragma unroll 8
        for (int j = p * 32; j < p * 32 + 32; ++j)
            s = fmaf(XS[j * 68 + rl], wA[j], s);
        s += __shfl_xor_sync(0xffffffffu, s, 1);
        s += __shfl_xor_sync(0xffffffffu, s, 2);
        if (p == 0) {
            int b = byi >> 7, i = byi & 127;
            g_rrow[((size_t)b * Rv + col0 + rl) * Mv + i] = s;
        }
    }
}

// ================= GEMM1 -> rel_guided (+fused rrow) =================
__global__ __launch_bounds__(256, 2) void k_gemm1(
    const float* __restrict__ rel_hs, float* __restrict__ rel_out,
    const float* __restrict__ ebeta, const float* __restrict__ egam,
    const float* __restrict__ ralpha) {
    extern __shared__ char base[];
    const uint32_t sm0 = s2u(base);
    const int tid = threadIdx.x, w = tid >> 5, L = tid & 31;
    const int r0 = blockIdx.x * 64;
    const int byi = blockIdx.y;

    __shared__ float betS[64], gamS[64], mS[128], sS[128];
    if (tid < 64) { betS[tid] = ebeta[r0 + tid]; gamS[tid] = egam[r0 + tid]; }
    if (tid < 128) {
        mS[tid] = g_mean_rel[byi * 128 + tid];
        sS[tid] = g_rstd_rel[byi * 128 + tid];
    }

    const int cRow = tid >> 3, cSeg = tid & 7;
    auto stage = [&](int ch, int st) {
        const int k0 = ch * 64;
        uint32_t s = sm0 + (uint32_t)(st * STGSZ);
        #pragma unroll
        for (int q = 0; q < 4; ++q) {
            int row = cRow + q * 32;
            cpa16(s + (uint32_t)row * 144 + cSeg * 16,
                  g_A1 + ((size_t)byi * 128 + row) * 768 + k0 + cSeg * 8);
            int src = r0 + (row >> 1) + (row & 1) * 768;
            cpa16(s + B_OFF + (uint32_t)row * 144 + cSeg * 16,
                  g_W1h + (size_t)src * 768 + k0 + cSeg * 8);
        }
    };

    gemm_body<true>(base, sm0, tid, w, L, stage,
                    rel_hs, rel_out, (size_t)byi * 128, r0, mS, sS, betS, gamS,
                    ralpha, byi);
}

// ================= GEMM2 -> ent_guided =================
__global__ __launch_bounds__(256, 2) void k_gemm2(
    const float* __restrict__ ent_hs, float* __restrict__ ent_out,
    const float* __restrict__ rbeta, const float* __restrict__ rgam) {
    extern __shared__ char base[];
    const uint32_t sm0 = s2u(base);
    const int tid = threadIdx.x, w = tid >> 5, L = tid & 31;
    const int e0 = blockIdx.x * 64;
    const int m0 = blockIdx.y * 128;

    __shared__ float betS[64], gamS[64], mS[128], sS[128];
    if (tid < 64) { betS[tid] = rbeta[e0 + tid]; gamS[tid] = rgam[e0 + tid]; }
    if (tid < 128) {
        mS[tid] = g_mean_ent[m0 + tid];
        sS[tid] = g_rstd_ent[m0 + tid];
    }

    const int cRow = tid >> 3, cSeg = tid & 7;
    auto stage = [&](int ch, int st) {
        const int k0 = ch * 64;
        uint32_t s = sm0 + (uint32_t)(st * STGSZ);
        #pragma unroll
        for (int q = 0; q < 4; ++q) {
            int row = cRow + q * 32;
            cpa16(s + (uint32_t)row * 144 + cSeg * 16,
                  g_cDh + (size_t)(m0 + row) * Rv + k0 + cSeg * 8);
            int src = e0 + (row >> 1) + (row & 1) * 768;
            cpa16(s + B_OFF + (uint32_t)row * 144 + cSeg * 16,
                  g_W2h + (size_t)src * 768 + k0 + cSeg * 8);
        }
    };

    gemm_body<false>(base, sm0, tid, w, L, stage,
                     ent_hs, ent_out, (size_t)m0, e0, mS, sS, betS, gamS,
                     nullptr, 0);
}

// ---------------- launch ----------------
extern "C" void kernel_launch(void* const* d_in, const int* in_sizes, int n_in,
                              void* d_out, int out_size) {
    const float* ent_hs    = (const float*)d_in[0];
    const float* rel_hs    = (const float*)d_in[1];
    const float* ent_alpha = (const float*)d_in[2];
    const float* ent_beta  = (const float*)d_in[3];
    const float* rel_alpha = (const float*)d_in[4];
    const float* rel_beta  = (const float*)d_in[5];
    const float* lam       = (const float*)d_in[6];
    const float* egr_Wb    = (const float*)d_in[7];
    const float* egr_Wg    = (const float*)d_in[8];
    const float* egr_beta  = (const float*)d_in[9];
    const float* egr_gamma = (const float*)d_in[10];
    const float* rge_Wb    = (const float*)d_in[11];
    const float* rge_Wg    = (const float*)d_in[12];
    const float* rge_beta  = (const float*)d_in[13];
    const float* rge_gamma = (const float*)d_in[14];
    const int*   mirror    = (const int*)d_in[15];
    const int*   upper     = (const int*)d_in[16];

    float* ent_out = (float*)d_out;                              // [B,S,E]
    float* rel_out = (float*)d_out + (size_t)Bc * Sv * Ev;       // [B,M,M,R]

    cudaFuncSetAttribute(k_gemm1, cudaFuncAttributeMaxDynamicSharedMemorySize, DSMEM);
    cudaFuncSetAttribute(k_gemm2, cudaFuncAttributeMaxDynamicSharedMemorySize, DSMEM);

    k_pre<<<NB_PRE, 256>>>(rel_hs, ent_hs, ent_alpha, ent_beta, rel_beta,
                           egr_Wb, egr_Wg, rge_Wb, rge_Wg);
    k_rowcol_ent<<<dim3(Bc * Mv, 3), 256>>>(ent_hs, mirror);
    k_actx<<<dim3(Bc * Mv, 2), 256>>>();
    k_gemm1<<<dim3(12, Bc * Mv), 256, DSMEM>>>(rel_hs, rel_out, egr_beta, egr_gamma, rel_alpha);
    k_rcol<<<Bc * Mv, 256>>>(rel_out);
    k_cond2<<<dim3((Sv + 127) / 128, Bc, 2), 256>>>(lam, upper);
    k_gemm2<<<dim3(12, (BSv + 127) / 128), 256, DSMEM>>>(ent_hs, ent_out, rge_beta, rge_gamma);
}